// round 2
// baseline (speedup 1.0000x reference)
#include <cuda_runtime.h>
#include <math.h>

// Problem constants
#define Bc 16
#define Nc 4096
#define Hc 8
#define Dc 64
#define Mc 128
#define BNHc 524288LL
#define BHc 128

#define SCALE_ 0.35355339059327373f   // 64^{-1/4}
#define RATIO_ 0.08838834764831845f   // 1/sqrt(128)
#define EPSF_ 1e-6f

// Output layout: [out1/out2 (BNH*64)] [v1p (BNH*128)] [v2p (BNH*128)]
#define V1P_OFF 33554432LL
#define V2P_OFF 100663296LL

// Scratch (device globals; no allocation allowed)
__device__ float    g_dash2[BNHc * Mc];    // dash - diag for keys (268 MB)
__device__ unsigned g_max2[BHc];           // per-(b,h) max of dash (monotonic uint key)
__device__ float    g_v2x[BHc * Mc * Dc];  // [bh][m][d] accumulator (4 MB)
__device__ float    g_v2sum[BHc * Mc];     // [bh][m]

__device__ __forceinline__ unsigned fkey(float f) {
    unsigned u = __float_as_uint(f);
    return (u & 0x80000000u) ? ~u : (u | 0x80000000u);
}
__device__ __forceinline__ float fdec(unsigned k) {
    return (k & 0x80000000u) ? __uint_as_float(k & 0x7fffffffu)
                             : __uint_as_float(~k);
}

// ---------------------------------------------------------------------------
// Kernel 0: reset accumulators (must happen every launch for determinism)
// ---------------------------------------------------------------------------
__global__ void k_init() {
    int i = blockIdx.x * blockDim.x + threadIdx.x;
    if (i < BHc * Mc * Dc) g_v2x[i] = 0.f;
    if (i < BHc * Mc)      g_v2sum[i] = 0.f;
    if (i < BHc)           g_max2[i] = 0u;
}

// ---------------------------------------------------------------------------
// Kernel 1: feature-map projection.
//   Q=true : queries -> v1p written directly to output (per-row max).
//   Q=false: keys    -> store (dash - diag) to g_dash2, atomicMax per (b,h).
// Per warp: 8 rows x 128 features register-blocked matvec; proj in smem with
// stride-65 rows (conflict-free scalar LDS), row tile in per-warp smem
// (broadcast reads), amortizing proj loads over 8 rows (FMA-bound by design).
// ---------------------------------------------------------------------------
template <bool Q>
__global__ void __launch_bounds__(256) k_feat(const float* __restrict__ src,
                                              const float* __restrict__ proj,
                                              float* __restrict__ out_q) {
    extern __shared__ float sm[];
    float* proj_s = sm;                                   // 128 * 65 floats
    float* rbuf = sm + 128 * 65 + (threadIdx.x >> 5) * 768;  // per-warp [k*12 + r]
    const int tid = threadIdx.x, lane = tid & 31;

    // Load proj[m][k] -> proj_s[m*65 + k] (coalesced LDG, conflict-free STS)
    for (int i = tid; i < Mc * Dc; i += 256) {
        int m = i >> 6, k = i & 63;
        proj_s[m * 65 + k] = proj[i];
    }
    __syncthreads();

    const long rowbase = (long)blockIdx.x * 64 + (tid >> 5) * 8;

    // Load 8 consecutive rows (512 contiguous floats) transposed into rbuf[k][r]
    const float4* s4 = (const float4*)(src + rowbase * 64);
    #pragma unroll
    for (int it = 0; it < 4; it++) {
        float4 v = s4[it * 32 + lane];
        int g = it * 128 + lane * 4;
        int r = g >> 6, k = g & 63;
        rbuf[(k + 0) * 12 + r] = v.x;
        rbuf[(k + 1) * 12 + r] = v.y;
        rbuf[(k + 2) * 12 + r] = v.z;
        rbuf[(k + 3) * 12 + r] = v.w;
    }
    __syncwarp();

    // diag = 0.5 * SCALE^2 * ||row||^2  (lanes 0..7 compute, then broadcast)
    float ss = 0.f;
    if (lane < 8) {
        #pragma unroll 8
        for (int k = 0; k < 64; k++) { float v = rbuf[k * 12 + lane]; ss += v * v; }
    }
    float dg[8];
    #pragma unroll
    for (int r = 0; r < 8; r++)
        dg[r] = 0.5f * SCALE_ * SCALE_ * __shfl_sync(0xffffffffu, ss, r);

    // Register-blocked matvec: lane owns m in {lane, lane+32, lane+64, lane+96}
    float acc[4][8];
    #pragma unroll
    for (int j = 0; j < 4; j++)
        #pragma unroll
        for (int r = 0; r < 8; r++) acc[j][r] = 0.f;

    #pragma unroll 4
    for (int k = 0; k < 64; k++) {
        float p[4];
        #pragma unroll
        for (int j = 0; j < 4; j++) p[j] = proj_s[(lane + 32 * j) * 65 + k];
        float rv[8];
        #pragma unroll
        for (int pr = 0; pr < 4; pr++) {
            float2 t = *(const float2*)&rbuf[k * 12 + 2 * pr];
            rv[2 * pr] = t.x; rv[2 * pr + 1] = t.y;
        }
        #pragma unroll
        for (int j = 0; j < 4; j++)
            #pragma unroll
            for (int r = 0; r < 8; r++)
                acc[j][r] = fmaf(p[j], rv[r], acc[j][r]);
    }

    // Epilogue per row
    #pragma unroll
    for (int r = 0; r < 8; r++) {
        float d0 = SCALE_ * acc[0][r], d1 = SCALE_ * acc[1][r];
        float d2 = SCALE_ * acc[2][r], d3 = SCALE_ * acc[3][r];
        float mx = fmaxf(fmaxf(d0, d1), fmaxf(d2, d3));
        #pragma unroll
        for (int o = 16; o > 0; o >>= 1)
            mx = fmaxf(mx, __shfl_xor_sync(0xffffffffu, mx, o));
        const long row = rowbase + r;
        if (Q) {
            float bia = dg[r] + mx;   // per-row max for queries
            out_q[row * 128 + lane     ] = RATIO_ * (__expf(d0 - bia) + EPSF_);
            out_q[row * 128 + lane + 32] = RATIO_ * (__expf(d1 - bia) + EPSF_);
            out_q[row * 128 + lane + 64] = RATIO_ * (__expf(d2 - bia) + EPSF_);
            out_q[row * 128 + lane + 96] = RATIO_ * (__expf(d3 - bia) + EPSF_);
        } else {
            float bia = dg[r];        // defer max subtraction to kernel 2
            g_dash2[row * 128 + lane     ] = d0 - bia;
            g_dash2[row * 128 + lane + 32] = d1 - bia;
            g_dash2[row * 128 + lane + 64] = d2 - bia;
            g_dash2[row * 128 + lane + 96] = d3 - bia;
            if (lane == 0) {
                int h  = (int)(row & 7);       // H = 8 innermost
                int bb = (int)(row >> 15);     // N*H = 32768
                atomicMax(&g_max2[bb * 8 + h], fkey(mx));
            }
        }
    }
}

// ---------------------------------------------------------------------------
// Kernel 2: v2p = ratio*(exp(dash2 - mx)+eps)  (written to output), plus
// rank-1 accumulation of v2x[bh][m][d] and v2sum[bh][m] over a 256-row chunk.
// Thread (tm = t&31, g = t>>5) owns m in {tm,tm+32,tm+64,tm+96} x d in [8g,8g+8).
// ---------------------------------------------------------------------------
__global__ void __launch_bounds__(256) k_v2(const float* __restrict__ x,
                                            float* __restrict__ outv2p) {
    __shared__ float v2p_s[4][128];
    __shared__ float xs[4][64];
    __shared__ float stage[128 * 65];

    const int bh = blockIdx.x >> 4;
    const int ch = blockIdx.x & 15;
    const int b = bh >> 3, h = bh & 7;
    const float mx = fdec(g_max2[bh]);
    const int tid = threadIdx.x;
    const int tm = tid & 31, gg = tid >> 5;
    const int mm = tid & 127;

    float acc[4][8];
    #pragma unroll
    for (int j = 0; j < 4; j++)
        #pragma unroll
        for (int dd = 0; dd < 8; dd++) acc[j][dd] = 0.f;
    float vsum = 0.f;

    for (int it = 0; it < 64; it++) {
        const long n0 = (long)ch * 256 + it * 4;
        // Stage v2p for 4 rows (and write it out), accumulate v2sum
        #pragma unroll
        for (int s = 0; s < 2; s++) {
            int idx = tid + s * 256;
            int rr = idx >> 7;
            long row = ((long)b * Nc + n0 + rr) * Hc + h;
            float t = g_dash2[row * 128 + mm];
            float v = RATIO_ * (__expf(t - mx) + EPSF_);
            v2p_s[rr][mm] = v;
            outv2p[row * 128 + mm] = v;
            vsum += v;
        }
        // Stage x for 4 rows
        {
            int rr = tid >> 6, kk = tid & 63;
            long row = ((long)b * Nc + n0 + rr) * Hc + h;
            xs[rr][kk] = x[row * 64 + kk];
        }
        __syncthreads();
        // Rank-1 updates
        #pragma unroll
        for (int rr = 0; rr < 4; rr++) {
            float4 xa = *(const float4*)&xs[rr][gg * 8];
            float4 xb = *(const float4*)&xs[rr][gg * 8 + 4];
            float xr[8] = {xa.x, xa.y, xa.z, xa.w, xb.x, xb.y, xb.z, xb.w};
            float pv[4] = {v2p_s[rr][tm], v2p_s[rr][tm + 32],
                           v2p_s[rr][tm + 64], v2p_s[rr][tm + 96]};
            #pragma unroll
            for (int j = 0; j < 4; j++)
                #pragma unroll
                for (int dd = 0; dd < 8; dd++)
                    acc[j][dd] = fmaf(pv[j], xr[dd], acc[j][dd]);
        }
        __syncthreads();
    }

    atomicAdd(&g_v2sum[bh * 128 + mm], vsum);

    // Stage accumulators through padded smem so the global atomics coalesce
    #pragma unroll
    for (int j = 0; j < 4; j++)
        #pragma unroll
        for (int dd = 0; dd < 8; dd++)
            stage[(tm + 32 * j) * 65 + gg * 8 + dd] = acc[j][dd];
    __syncthreads();
    for (int idx = tid; idx < 8192; idx += 256) {
        int m = idx >> 6, dd = idx & 63;
        atomicAdd(&g_v2x[bh * 8192 + idx], stage[m * 65 + dd]);
    }
}

// ---------------------------------------------------------------------------
// Kernel 3: out1[row][d] = sum_m v1p[row][m] * v2x[bh][m][d], normalized by
// out2 = sum_m v1p[row][m] * v2sum[bh][m].
// v2x tile lives in registers: thread (dd = t&63, mr = t>>6) holds 16 m-values
// of column dd. Per row: 16 FMA/thread + smem tree reduce over 8 partials.
// v1p rows double-buffered via dedicated staging warp.
// ---------------------------------------------------------------------------
__global__ void __launch_bounds__(512) k_out(const float* __restrict__ v1p,
                                             float* __restrict__ out1) {
    __shared__ float v1a[128], v1b[128];
    __shared__ float red[8 * 68];
    __shared__ float red2[8];

    const int bh = blockIdx.x >> 4, ch = blockIdx.x & 15;
    const int b = bh >> 3, h = bh & 7;
    const int tid = threadIdx.x;
    const int dd = tid & 63, mr = tid >> 6;

    float vx[16];
    #pragma unroll
    for (int km = 0; km < 16; km++)
        vx[km] = g_v2x[bh * 8192 + (mr * 16 + km) * 64 + dd];
    float vs[16];
    #pragma unroll
    for (int km = 0; km < 16; km++)
        vs[km] = (dd == 0) ? g_v2sum[bh * 128 + mr * 16 + km] : 0.f;

    const long row0 = ((long)b * Nc + (long)ch * 256) * Hc + h;
    if (tid >= 64 && tid < 96)
        ((float4*)v1a)[tid - 64] = ((const float4*)(v1p + row0 * 128))[tid - 64];
    __syncthreads();

    float* cur = v1a; float* nxt = v1b;
    for (int i = 0; i < 256; i++) {
        const long row = row0 + (long)i * 8;
        float s = 0.f;
        #pragma unroll
        for (int km = 0; km < 16; km++)
            s = fmaf(cur[mr * 16 + km], vx[km], s);
        red[mr * 68 + dd] = s;
        if (dd == 0) {
            float s2 = 0.f;
            #pragma unroll
            for (int km = 0; km < 16; km++)
                s2 = fmaf(cur[mr * 16 + km], vs[km], s2);
            red2[mr] = s2;
        }
        __syncthreads();
        if (tid < 64) {
            float o1 = 0.f, o2 = 0.f;
            #pragma unroll
            for (int q = 0; q < 8; q++) { o1 += red[q * 68 + tid]; o2 += red2[q]; }
            out1[row * 64 + tid] = o1 / o2;
        } else if (tid < 96 && i + 1 < 256) {
            ((float4*)nxt)[tid - 64] =
                ((const float4*)(v1p + (row + 8) * 128))[tid - 64];
        }
        __syncthreads();
        float* t = cur; cur = nxt; nxt = t;
    }
}

// ---------------------------------------------------------------------------
extern "C" void kernel_launch(void* const* d_in, const int* in_sizes, int n_in,
                              void* d_out, int out_size) {
    const float* x    = (const float*)d_in[0];
    const float* nv1  = (const float*)d_in[1];
    const float* nv2  = (const float*)d_in[2];
    const float* proj = (const float*)d_in[3];
    float* out = (float*)d_out;

    const int smem_feat = (128 * 65 + 8 * 768) * 4;  // 57856 B
    cudaFuncSetAttribute(k_feat<true>,  cudaFuncAttributeMaxDynamicSharedMemorySize, smem_feat);
    cudaFuncSetAttribute(k_feat<false>, cudaFuncAttributeMaxDynamicSharedMemorySize, smem_feat);

    k_init<<<4096, 256>>>();
    k_feat<false><<<8192, 256, smem_feat>>>(nv2, proj, nullptr);        // keys
    k_feat<true ><<<8192, 256, smem_feat>>>(nv1, proj, out + V1P_OFF);  // queries
    k_v2 <<<2048, 256>>>(x, out + V2P_OFF);
    k_out<<<2048, 512>>>(out + V1P_OFF, out);
}

// round 3
// speedup vs baseline: 1.2530x; 1.2530x over previous
#include <cuda_runtime.h>
#include <cuda_bf16.h>
#include <math.h>

// Problem constants
#define Bc 16
#define Nc 4096
#define Hc 8
#define Dc 64
#define Mc 128
#define BNHc 524288LL
#define BHc 128

#define SCALE_ 0.35355339059327373f   // 64^{-1/4}
#define RATIO_ 0.08838834764831845f   // 1/sqrt(128)
#define EPSF_ 1e-6f

// Output layout: [out1/out2 (BNH*64)] [v1p (BNH*128)] [v2p (BNH*128)]
#define V1P_OFF 33554432LL
#define V2P_OFF 100663296LL

// Scratch (device globals; no allocation allowed)
__device__ float    g_dash2[BNHc * Mc];    // dash - diag for keys (268 MB)
__device__ unsigned g_max2[BHc];           // per-(b,h) max of dash (monotonic uint key)
__device__ float    g_v2x[BHc * Mc * Dc];  // [bh][m][d] accumulator (4 MB)
__device__ float    g_v2sum[BHc * Mc];     // [bh][m]

__device__ __forceinline__ unsigned fkey(float f) {
    unsigned u = __float_as_uint(f);
    return (u & 0x80000000u) ? ~u : (u | 0x80000000u);
}
__device__ __forceinline__ float fdec(unsigned k) {
    return (k & 0x80000000u) ? __uint_as_float(k & 0x7fffffffu)
                             : __uint_as_float(~k);
}

__device__ __forceinline__ void split2(float v, __nv_bfloat16* hi, __nv_bfloat16* lo) {
    __nv_bfloat16 h = __float2bfloat16(v);
    *hi = h;
    *lo = __float2bfloat16(v - __bfloat162float(h));
}

__device__ __forceinline__ void mma_bf16(float c[4], unsigned a0, unsigned a1,
                                         unsigned a2, unsigned a3,
                                         unsigned b0, unsigned b1) {
    asm volatile(
        "mma.sync.aligned.m16n8k16.row.col.f32.bf16.bf16.f32 "
        "{%0,%1,%2,%3}, {%4,%5,%6,%7}, {%8,%9}, {%0,%1,%2,%3};"
        : "+f"(c[0]), "+f"(c[1]), "+f"(c[2]), "+f"(c[3])
        : "r"(a0), "r"(a1), "r"(a2), "r"(a3), "r"(b0), "r"(b1));
}

// ---------------------------------------------------------------------------
// Kernel 0: reset accumulators
// ---------------------------------------------------------------------------
__global__ void k_init() {
    int i = blockIdx.x * blockDim.x + threadIdx.x;
    if (i < BHc * Mc * Dc) g_v2x[i] = 0.f;
    if (i < BHc * Mc)      g_v2sum[i] = 0.f;
    if (i < BHc)           g_max2[i] = 0u;
}

// ---------------------------------------------------------------------------
// Kernel 1: feature-map projection on tensor cores (bf16x3 split MMA).
// Block = 256 threads (8 warps), 128 rows. Warp w computes rows 16w..16w+15
// x all 128 features via m16n8k16 mma: 4 k-steps x 16 n-tiles x 3 (hi*hi,
// hi*lo, lo*hi). A = data*SCALE split to bf16 hi/lo in smem (stride 72,
// conflict-free LDS.32 frag loads), B = proj split likewise.
//   Q=true : per-row max, exp -> v1p output.
//   Q=false: dash-diag -> g_dash2, per-(b,h) max -> g_max2 via atomicMax.
// ---------------------------------------------------------------------------
#define AST 72   // smem k-stride (bf16 elems)

template <bool Q>
__global__ void __launch_bounds__(256, 2) k_feat(const float* __restrict__ src,
                                                 const float* __restrict__ proj,
                                                 float* __restrict__ out_q) {
    extern __shared__ char smraw[];
    __nv_bfloat16* A_hi = (__nv_bfloat16*)smraw;                  // 128*72
    __nv_bfloat16* A_lo = A_hi + 128 * AST;
    __nv_bfloat16* B_hi = A_lo + 128 * AST;                       // 128*72
    __nv_bfloat16* B_lo = B_hi + 128 * AST;
    float*    diag_s   = (float*)(B_lo + 128 * AST);              // [128]
    float*    rowmax_s = diag_s + 128;                            // [128]
    unsigned* hmax_u   = (unsigned*)(rowmax_s + 128);             // [8]

    const int tid = threadIdx.x, lane = tid & 31, wid = tid >> 5;
    const long rowbase = (long)blockIdx.x * 128;

    if (!Q && tid < 8) hmax_u[tid] = 0u;

    // Load A: thread t handles row=t>>1, k in [32*(t&1), +32). Scale + split +
    // per-row sumsq (diag).
    {
        const int row = tid >> 1, kb = (tid & 1) * 32;
        const float4* s4 = (const float4*)(src + (rowbase + row) * 64 + kb);
        float ss = 0.f;
        #pragma unroll
        for (int i = 0; i < 8; i++) {
            float4 v = s4[i];
            float e[4] = {v.x * SCALE_, v.y * SCALE_, v.z * SCALE_, v.w * SCALE_};
            #pragma unroll
            for (int e2 = 0; e2 < 4; e2++) {
                ss += e[e2] * e[e2];
                split2(e[e2], &A_hi[row * AST + kb + i * 4 + e2],
                              &A_lo[row * AST + kb + i * 4 + e2]);
            }
        }
        ss += __shfl_xor_sync(0xffffffffu, ss, 1);
        if ((tid & 1) == 0) diag_s[row] = 0.5f * ss;
    }
    // Load B (proj [m][k]): same pattern, no scale.
    {
        const int m = tid >> 1, kb = (tid & 1) * 32;
        const float4* p4 = (const float4*)(proj + m * 64 + kb);
        #pragma unroll
        for (int i = 0; i < 8; i++) {
            float4 v = p4[i];
            float e[4] = {v.x, v.y, v.z, v.w};
            #pragma unroll
            for (int e2 = 0; e2 < 4; e2++)
                split2(e[e2], &B_hi[m * AST + kb + i * 4 + e2],
                              &B_lo[m * AST + kb + i * 4 + e2]);
        }
    }
    __syncthreads();

    const int grp = lane >> 2, q2 = (lane & 3) * 2;
    const int r1 = wid * 16 + grp;       // local rows
    const int r2 = r1 + 8;

    float acc[16][4];
    #pragma unroll
    for (int nt = 0; nt < 16; nt++)
        #pragma unroll
        for (int j = 0; j < 4; j++) acc[nt][j] = 0.f;

    #pragma unroll
    for (int ks = 0; ks < 4; ks++) {
        const int k0 = ks * 16;
        unsigned ah[4], al[4];
        ah[0] = *(const unsigned*)&A_hi[r1 * AST + k0 + q2];
        ah[1] = *(const unsigned*)&A_hi[r2 * AST + k0 + q2];
        ah[2] = *(const unsigned*)&A_hi[r1 * AST + k0 + q2 + 8];
        ah[3] = *(const unsigned*)&A_hi[r2 * AST + k0 + q2 + 8];
        al[0] = *(const unsigned*)&A_lo[r1 * AST + k0 + q2];
        al[1] = *(const unsigned*)&A_lo[r2 * AST + k0 + q2];
        al[2] = *(const unsigned*)&A_lo[r1 * AST + k0 + q2 + 8];
        al[3] = *(const unsigned*)&A_lo[r2 * AST + k0 + q2 + 8];
        #pragma unroll
        for (int nt = 0; nt < 16; nt++) {
            const int n = nt * 8 + grp;
            unsigned bh0 = *(const unsigned*)&B_hi[n * AST + k0 + q2];
            unsigned bh1 = *(const unsigned*)&B_hi[n * AST + k0 + q2 + 8];
            unsigned bl0 = *(const unsigned*)&B_lo[n * AST + k0 + q2];
            unsigned bl1 = *(const unsigned*)&B_lo[n * AST + k0 + q2 + 8];
            mma_bf16(acc[nt], ah[0], ah[1], ah[2], ah[3], bh0, bh1);
            mma_bf16(acc[nt], ah[0], ah[1], ah[2], ah[3], bl0, bl1);
            mma_bf16(acc[nt], al[0], al[1], al[2], al[3], bh0, bh1);
        }
    }

    // Per-row max over all 128 features (lane holds cols q2,q2+1 per tile).
    float mx1 = -1e30f, mx2 = -1e30f;
    #pragma unroll
    for (int nt = 0; nt < 16; nt++) {
        mx1 = fmaxf(mx1, fmaxf(acc[nt][0], acc[nt][1]));
        mx2 = fmaxf(mx2, fmaxf(acc[nt][2], acc[nt][3]));
    }
    mx1 = fmaxf(mx1, __shfl_xor_sync(0xffffffffu, mx1, 1));
    mx1 = fmaxf(mx1, __shfl_xor_sync(0xffffffffu, mx1, 2));
    mx2 = fmaxf(mx2, __shfl_xor_sync(0xffffffffu, mx2, 1));
    mx2 = fmaxf(mx2, __shfl_xor_sync(0xffffffffu, mx2, 2));

    const float d1 = diag_s[r1], d2 = diag_s[r2];
    const long grow1 = rowbase + r1, grow2 = rowbase + r2;

    if (Q) {
        const float b1 = d1 + mx1, b2 = d2 + mx2;
        #pragma unroll
        for (int nt = 0; nt < 16; nt++) {
            float2 o1 = make_float2(RATIO_ * (__expf(acc[nt][0] - b1) + EPSF_),
                                    RATIO_ * (__expf(acc[nt][1] - b1) + EPSF_));
            float2 o2 = make_float2(RATIO_ * (__expf(acc[nt][2] - b2) + EPSF_),
                                    RATIO_ * (__expf(acc[nt][3] - b2) + EPSF_));
            *(float2*)&out_q[grow1 * 128 + nt * 8 + q2] = o1;
            *(float2*)&out_q[grow2 * 128 + nt * 8 + q2] = o2;
        }
    } else {
        #pragma unroll
        for (int nt = 0; nt < 16; nt++) {
            float2 o1 = make_float2(acc[nt][0] - d1, acc[nt][1] - d1);
            float2 o2 = make_float2(acc[nt][2] - d2, acc[nt][3] - d2);
            *(float2*)&g_dash2[grow1 * 128 + nt * 8 + q2] = o1;
            *(float2*)&g_dash2[grow2 * 128 + nt * 8 + q2] = o2;
        }
        if ((lane & 3) == 0) { rowmax_s[r1] = mx1; rowmax_s[r2] = mx2; }
        __syncthreads();
        if (tid < 128)
            atomicMax(&hmax_u[tid & 7], fkey(rowmax_s[tid]));   // h = row&7
        __syncthreads();
        if (tid < 8)
            atomicMax(&g_max2[(int)(rowbase >> 15) * 8 + tid], hmax_u[tid]);
    }
}

// ---------------------------------------------------------------------------
// Kernel 2: v2p = ratio*(exp(dash2 - mx)+eps)  (written to output), plus
// rank-1 accumulation of v2x[bh][m][d] and v2sum[bh][m] over a 256-row chunk.
// 8 rows per barrier pair.
// ---------------------------------------------------------------------------
__global__ void __launch_bounds__(256) k_v2(const float* __restrict__ x,
                                            float* __restrict__ outv2p) {
    __shared__ float v2p_s[8][128];
    __shared__ float xs[8][64];
    __shared__ float stage[128 * 65];

    const int bh = blockIdx.x >> 4;
    const int ch = blockIdx.x & 15;
    const int b = bh >> 3, h = bh & 7;
    const float mx = fdec(g_max2[bh]);
    const int tid = threadIdx.x;
    const int tm = tid & 31, gg = tid >> 5;
    const int mm = tid & 127;

    float acc[4][8];
    #pragma unroll
    for (int j = 0; j < 4; j++)
        #pragma unroll
        for (int dd = 0; dd < 8; dd++) acc[j][dd] = 0.f;
    float vsum = 0.f;

    for (int it = 0; it < 32; it++) {
        const long n0 = (long)ch * 256 + it * 8;
        // Stage v2p for 8 rows (and write it out), accumulate v2sum
        #pragma unroll
        for (int s = 0; s < 4; s++) {
            int rr = (tid >> 7) + s * 2;
            long row = ((long)b * Nc + n0 + rr) * Hc + h;
            float t = g_dash2[row * 128 + mm];
            float v = RATIO_ * (__expf(t - mx) + EPSF_);
            v2p_s[rr][mm] = v;
            outv2p[row * 128 + mm] = v;
            vsum += v;
        }
        // Stage x for 8 rows
        #pragma unroll
        for (int s = 0; s < 2; s++) {
            int rr = (tid >> 6) + s * 4, kk = tid & 63;
            long row = ((long)b * Nc + n0 + rr) * Hc + h;
            xs[rr][kk] = x[row * 64 + kk];
        }
        __syncthreads();
        // Rank-1 updates
        #pragma unroll
        for (int rr = 0; rr < 8; rr++) {
            float4 xa = *(const float4*)&xs[rr][gg * 8];
            float4 xb = *(const float4*)&xs[rr][gg * 8 + 4];
            float xr[8] = {xa.x, xa.y, xa.z, xa.w, xb.x, xb.y, xb.z, xb.w};
            float pv[4] = {v2p_s[rr][tm], v2p_s[rr][tm + 32],
                           v2p_s[rr][tm + 64], v2p_s[rr][tm + 96]};
            #pragma unroll
            for (int j = 0; j < 4; j++)
                #pragma unroll
                for (int dd = 0; dd < 8; dd++)
                    acc[j][dd] = fmaf(pv[j], xr[dd], acc[j][dd]);
        }
        __syncthreads();
    }

    atomicAdd(&g_v2sum[bh * 128 + mm], vsum);

    // Stage accumulators through padded smem so the global atomics coalesce
    #pragma unroll
    for (int j = 0; j < 4; j++)
        #pragma unroll
        for (int dd = 0; dd < 8; dd++)
            stage[(tm + 32 * j) * 65 + gg * 8 + dd] = acc[j][dd];
    __syncthreads();
    for (int idx = tid; idx < 8192; idx += 256) {
        int m = idx >> 6, dd = idx & 63;
        atomicAdd(&g_v2x[bh * 8192 + idx], stage[m * 65 + dd]);
    }
}

// ---------------------------------------------------------------------------
// Kernel 3: out1[row][d] = sum_m v1p[row][m] * v2x[bh][m][d], normalized by
// out2 = sum_m v1p[row][m] * v2sum[bh][m].  4 rows per barrier pair.
// ---------------------------------------------------------------------------
__global__ void __launch_bounds__(512) k_out(const float* __restrict__ v1p,
                                             float* __restrict__ out1) {
    __shared__ float v1a[4 * 128], v1b[4 * 128];
    __shared__ float red[4 * 8 * 68];
    __shared__ float red2[4 * 8];

    const int bh = blockIdx.x >> 4, ch = blockIdx.x & 15;
    const int b = bh >> 3, h = bh & 7;
    const int tid = threadIdx.x;
    const int dd = tid & 63, mr = tid >> 6;

    float vx[16];
    #pragma unroll
    for (int km = 0; km < 16; km++)
        vx[km] = g_v2x[bh * 8192 + (mr * 16 + km) * 64 + dd];
    float vs[16];
    #pragma unroll
    for (int km = 0; km < 16; km++)
        vs[km] = (dd == 0) ? g_v2sum[bh * 128 + mr * 16 + km] : 0.f;

    const long row0 = ((long)b * Nc + (long)ch * 256) * Hc + h;
    if (tid >= 128 && tid < 256) {
        int idx = tid - 128, j = idx >> 5, off = idx & 31;
        ((float4*)v1a)[idx] = ((const float4*)(v1p + (row0 + (long)j * 8) * 128))[off];
    }
    __syncthreads();

    float* cur = v1a; float* nxt = v1b;
    for (int i = 0; i < 64; i++) {
        float s[4];
        #pragma unroll
        for (int j = 0; j < 4; j++) {
            float t = 0.f;
            #pragma unroll
            for (int km = 0; km < 16; km++)
                t = fmaf(cur[j * 128 + mr * 16 + km], vx[km], t);
            s[j] = t;
            red[(j * 8 + mr) * 68 + dd] = t;
        }
        if (dd == 0) {
            #pragma unroll
            for (int j = 0; j < 4; j++) {
                float s2 = 0.f;
                #pragma unroll
                for (int km = 0; km < 16; km++)
                    s2 = fmaf(cur[j * 128 + mr * 16 + km], vs[km], s2);
                red2[j * 8 + mr] = s2;
            }
        }
        __syncthreads();
        if (tid < 64) {
            #pragma unroll
            for (int j = 0; j < 4; j++) {
                float o1 = 0.f, o2 = 0.f;
                #pragma unroll
                for (int q = 0; q < 8; q++) {
                    o1 += red[(j * 8 + q) * 68 + tid];
                    o2 += red2[j * 8 + q];
                }
                out1[(row0 + (long)(4 * i + j) * 8) * 64 + tid] = o1 / o2;
            }
        } else if (tid >= 128 && tid < 256 && i + 1 < 64) {
            int idx = tid - 128, j = idx >> 5, off = idx & 31;
            ((float4*)nxt)[idx] =
                ((const float4*)(v1p + (row0 + (long)(4 * (i + 1) + j) * 8) * 128))[off];
        }
        __syncthreads();
        float* t = cur; cur = nxt; nxt = t;
    }
}

// ---------------------------------------------------------------------------
extern "C" void kernel_launch(void* const* d_in, const int* in_sizes, int n_in,
                              void* d_out, int out_size) {
    const float* x    = (const float*)d_in[0];
    const float* nv1  = (const float*)d_in[1];
    const float* nv2  = (const float*)d_in[2];
    const float* proj = (const float*)d_in[3];
    float* out = (float*)d_out;

    const int smem_feat = 4 * 128 * AST * 2 + 2 * 128 * 4 + 8 * 4;  // 74784 B
    cudaFuncSetAttribute(k_feat<true>,  cudaFuncAttributeMaxDynamicSharedMemorySize, smem_feat);
    cudaFuncSetAttribute(k_feat<false>, cudaFuncAttributeMaxDynamicSharedMemorySize, smem_feat);

    k_init<<<4096, 256>>>();
    k_feat<false><<<4096, 256, smem_feat>>>(nv2, proj, nullptr);        // keys
    k_feat<true ><<<4096, 256, smem_feat>>>(nv1, proj, out + V1P_OFF);  // queries
    k_v2 <<<2048, 256>>>(x, out + V2P_OFF);
    k_out<<<2048, 512>>>(out + V1P_OFF, out);
}

// round 4
// speedup vs baseline: 1.4931x; 1.1916x over previous
#include <cuda_runtime.h>
#include <cuda_bf16.h>
#include <math.h>

// Problem constants
#define Bc 16
#define Nc 4096
#define Hc 8
#define Dc 64
#define Mc 128
#define BNHc 524288LL
#define BHc 128

#define SCALE_ 0.35355339059327373f   // 64^{-1/4}
#define RATIO_ 0.08838834764831845f   // 1/sqrt(128)
#define EPSF_ 1e-6f

// Output layout: [out1/out2 (BNH*64)] [v1p (BNH*128)] [v2p (BNH*128)]
#define V1P_OFF 33554432LL
#define V2P_OFF 100663296LL

// Scratch (device globals; no allocation allowed)
__device__ float    g_dash2[BNHc * Mc];    // dash - diag for keys (268 MB)
__device__ unsigned g_max2[BHc];           // per-(b,h) max of dash
__device__ float    g_v2x[BHc * Mc * Dc];  // [bh][m][d] accumulator (4 MB)
__device__ float    g_v2sum[BHc * Mc];     // [bh][m]

__device__ __forceinline__ unsigned fkey(float f) {
    unsigned u = __float_as_uint(f);
    return (u & 0x80000000u) ? ~u : (u | 0x80000000u);
}
__device__ __forceinline__ float fdec(unsigned k) {
    return (k & 0x80000000u) ? __uint_as_float(k & 0x7fffffffu)
                             : __uint_as_float(~k);
}

__device__ __forceinline__ void split2(float v, __nv_bfloat16* hi, __nv_bfloat16* lo) {
    __nv_bfloat16 h = __float2bfloat16(v);
    *hi = h;
    *lo = __float2bfloat16(v - __bfloat162float(h));
}

__device__ __forceinline__ void mma_bf16(float c[4], unsigned a0, unsigned a1,
                                         unsigned a2, unsigned a3,
                                         unsigned b0, unsigned b1) {
    asm volatile(
        "mma.sync.aligned.m16n8k16.row.col.f32.bf16.bf16.f32 "
        "{%0,%1,%2,%3}, {%4,%5,%6,%7}, {%8,%9}, {%0,%1,%2,%3};"
        : "+f"(c[0]), "+f"(c[1]), "+f"(c[2]), "+f"(c[3])
        : "r"(a0), "r"(a1), "r"(a2), "r"(a3), "r"(b0), "r"(b1));
}

// ---------------------------------------------------------------------------
// Kernel 0: reset accumulators
// ---------------------------------------------------------------------------
__global__ void k_init() {
    int i = blockIdx.x * blockDim.x + threadIdx.x;
    if (i < BHc * Mc * Dc) g_v2x[i] = 0.f;
    if (i < BHc * Mc)      g_v2sum[i] = 0.f;
    if (i < BHc)           g_max2[i] = 0u;
}

// ---------------------------------------------------------------------------
// Kernel 1: feature-map projection on tensor cores (bf16x3 split MMA).
// (unchanged from R3 — proven)
// ---------------------------------------------------------------------------
#define AST 72   // smem k-stride (bf16 elems)

template <bool Q>
__global__ void __launch_bounds__(256, 2) k_feat(const float* __restrict__ src,
                                                 const float* __restrict__ proj,
                                                 float* __restrict__ out_q) {
    extern __shared__ char smraw[];
    __nv_bfloat16* A_hi = (__nv_bfloat16*)smraw;                  // 128*72
    __nv_bfloat16* A_lo = A_hi + 128 * AST;
    __nv_bfloat16* B_hi = A_lo + 128 * AST;                       // 128*72
    __nv_bfloat16* B_lo = B_hi + 128 * AST;
    float*    diag_s   = (float*)(B_lo + 128 * AST);              // [128]
    float*    rowmax_s = diag_s + 128;                            // [128]
    unsigned* hmax_u   = (unsigned*)(rowmax_s + 128);             // [8]

    const int tid = threadIdx.x, lane = tid & 31, wid = tid >> 5;
    const long rowbase = (long)blockIdx.x * 128;

    if (!Q && tid < 8) hmax_u[tid] = 0u;

    {
        const int row = tid >> 1, kb = (tid & 1) * 32;
        const float4* s4 = (const float4*)(src + (rowbase + row) * 64 + kb);
        float ss = 0.f;
        #pragma unroll
        for (int i = 0; i < 8; i++) {
            float4 v = s4[i];
            float e[4] = {v.x * SCALE_, v.y * SCALE_, v.z * SCALE_, v.w * SCALE_};
            #pragma unroll
            for (int e2 = 0; e2 < 4; e2++) {
                ss += e[e2] * e[e2];
                split2(e[e2], &A_hi[row * AST + kb + i * 4 + e2],
                              &A_lo[row * AST + kb + i * 4 + e2]);
            }
        }
        ss += __shfl_xor_sync(0xffffffffu, ss, 1);
        if ((tid & 1) == 0) diag_s[row] = 0.5f * ss;
    }
    {
        const int m = tid >> 1, kb = (tid & 1) * 32;
        const float4* p4 = (const float4*)(proj + m * 64 + kb);
        #pragma unroll
        for (int i = 0; i < 8; i++) {
            float4 v = p4[i];
            float e[4] = {v.x, v.y, v.z, v.w};
            #pragma unroll
            for (int e2 = 0; e2 < 4; e2++)
                split2(e[e2], &B_hi[m * AST + kb + i * 4 + e2],
                              &B_lo[m * AST + kb + i * 4 + e2]);
        }
    }
    __syncthreads();

    const int grp = lane >> 2, q2 = (lane & 3) * 2;
    const int r1 = wid * 16 + grp;
    const int r2 = r1 + 8;

    float acc[16][4];
    #pragma unroll
    for (int nt = 0; nt < 16; nt++)
        #pragma unroll
        for (int j = 0; j < 4; j++) acc[nt][j] = 0.f;

    #pragma unroll
    for (int ks = 0; ks < 4; ks++) {
        const int k0 = ks * 16;
        unsigned ah[4], al[4];
        ah[0] = *(const unsigned*)&A_hi[r1 * AST + k0 + q2];
        ah[1] = *(const unsigned*)&A_hi[r2 * AST + k0 + q2];
        ah[2] = *(const unsigned*)&A_hi[r1 * AST + k0 + q2 + 8];
        ah[3] = *(const unsigned*)&A_hi[r2 * AST + k0 + q2 + 8];
        al[0] = *(const unsigned*)&A_lo[r1 * AST + k0 + q2];
        al[1] = *(const unsigned*)&A_lo[r2 * AST + k0 + q2];
        al[2] = *(const unsigned*)&A_lo[r1 * AST + k0 + q2 + 8];
        al[3] = *(const unsigned*)&A_lo[r2 * AST + k0 + q2 + 8];
        #pragma unroll
        for (int nt = 0; nt < 16; nt++) {
            const int n = nt * 8 + grp;
            unsigned bh0 = *(const unsigned*)&B_hi[n * AST + k0 + q2];
            unsigned bh1 = *(const unsigned*)&B_hi[n * AST + k0 + q2 + 8];
            unsigned bl0 = *(const unsigned*)&B_lo[n * AST + k0 + q2];
            unsigned bl1 = *(const unsigned*)&B_lo[n * AST + k0 + q2 + 8];
            mma_bf16(acc[nt], ah[0], ah[1], ah[2], ah[3], bh0, bh1);
            mma_bf16(acc[nt], ah[0], ah[1], ah[2], ah[3], bl0, bl1);
            mma_bf16(acc[nt], al[0], al[1], al[2], al[3], bh0, bh1);
        }
    }

    float mx1 = -1e30f, mx2 = -1e30f;
    #pragma unroll
    for (int nt = 0; nt < 16; nt++) {
        mx1 = fmaxf(mx1, fmaxf(acc[nt][0], acc[nt][1]));
        mx2 = fmaxf(mx2, fmaxf(acc[nt][2], acc[nt][3]));
    }
    mx1 = fmaxf(mx1, __shfl_xor_sync(0xffffffffu, mx1, 1));
    mx1 = fmaxf(mx1, __shfl_xor_sync(0xffffffffu, mx1, 2));
    mx2 = fmaxf(mx2, __shfl_xor_sync(0xffffffffu, mx2, 1));
    mx2 = fmaxf(mx2, __shfl_xor_sync(0xffffffffu, mx2, 2));

    const float d1 = diag_s[r1], d2 = diag_s[r2];
    const long grow1 = rowbase + r1, grow2 = rowbase + r2;

    if (Q) {
        const float b1 = d1 + mx1, b2 = d2 + mx2;
        #pragma unroll
        for (int nt = 0; nt < 16; nt++) {
            float2 o1 = make_float2(RATIO_ * (__expf(acc[nt][0] - b1) + EPSF_),
                                    RATIO_ * (__expf(acc[nt][1] - b1) + EPSF_));
            float2 o2 = make_float2(RATIO_ * (__expf(acc[nt][2] - b2) + EPSF_),
                                    RATIO_ * (__expf(acc[nt][3] - b2) + EPSF_));
            *(float2*)&out_q[grow1 * 128 + nt * 8 + q2] = o1;
            *(float2*)&out_q[grow2 * 128 + nt * 8 + q2] = o2;
        }
    } else {
        #pragma unroll
        for (int nt = 0; nt < 16; nt++) {
            float2 o1 = make_float2(acc[nt][0] - d1, acc[nt][1] - d1);
            float2 o2 = make_float2(acc[nt][2] - d2, acc[nt][3] - d2);
            *(float2*)&g_dash2[grow1 * 128 + nt * 8 + q2] = o1;
            *(float2*)&g_dash2[grow2 * 128 + nt * 8 + q2] = o2;
        }
        if ((lane & 3) == 0) { rowmax_s[r1] = mx1; rowmax_s[r2] = mx2; }
        __syncthreads();
        if (tid < 128)
            atomicMax(&hmax_u[tid & 7], fkey(rowmax_s[tid]));
        __syncthreads();
        if (tid < 8)
            atomicMax(&g_max2[(int)(rowbase >> 15) * 8 + tid], hmax_u[tid]);
    }
}

// ---------------------------------------------------------------------------
// Kernel 2 (NEW, tensor cores): per (bh, 256-row chunk):
//   v2p = ratio*(exp(dash2 - mx)+eps) -> output (fp32) + bf16 split transposed
//   v2x[m][d] (+ v2sum via ones-column n=64) = v2p^T x, bf16x3 MMA,
//   M=m(128), N=72 (64 d + ones + pad), K=rows (4 tiles of 64).
// Strides = 72 -> conflict-free fragment LDS.
// ---------------------------------------------------------------------------
#define KV2 72

__global__ void __launch_bounds__(256) k_v2(const float* __restrict__ x,
                                            float* __restrict__ outv2p) {
    extern __shared__ char smraw[];
    __nv_bfloat16* vpT_hi = (__nv_bfloat16*)smraw;        // [128][KV2]
    __nv_bfloat16* vpT_lo = vpT_hi + 128 * KV2;
    __nv_bfloat16* xT_hi  = vpT_lo + 128 * KV2;           // [72][KV2]
    __nv_bfloat16* xT_lo  = xT_hi + 72 * KV2;

    const int bh = blockIdx.x >> 4, ch = blockIdx.x & 15;
    const int b = bh >> 3, h = bh & 7;
    const float mx = fdec(g_max2[bh]);
    const int tid = threadIdx.x, lane = tid & 31, wid = tid >> 5;
    const int grp = lane >> 2, q2 = (lane & 3) * 2;
    const long nbase = (long)b * Nc + (long)ch * 256;

    // ones column (n=64) and zero rows (n=65..71), written once
    #pragma unroll
    for (int j = 0; j < 2; j++) {
        int idx = tid + j * 256;           // 0..511
        int n = 64 + (idx >> 6), r = idx & 63;
        xT_hi[n * KV2 + r] = (n == 64) ? __float2bfloat16(1.0f) : __float2bfloat16(0.0f);
        xT_lo[n * KV2 + r] = __float2bfloat16(0.0f);
    }

    float acc[9][4];
    #pragma unroll
    for (int nt = 0; nt < 9; nt++)
        #pragma unroll
        for (int j = 0; j < 4; j++) acc[nt][j] = 0.f;

    const int m1 = wid * 16 + grp, m2 = m1 + 8;

    for (int t = 0; t < 4; t++) {
        const long r0 = nbase + t * 64;
        // v2p: exp + global write + transposed bf16 split
        #pragma unroll
        for (int j = 0; j < 32; j++) {
            int idx = tid + j * 256;
            int r = idx >> 7, m = idx & 127;
            long grow = (r0 + r) * Hc + h;
            float v = RATIO_ * (__expf(g_dash2[grow * 128 + m] - mx) + EPSF_);
            outv2p[grow * 128 + m] = v;
            split2(v, &vpT_hi[m * KV2 + r], &vpT_lo[m * KV2 + r]);
        }
        // x: transposed bf16 split
        #pragma unroll
        for (int j = 0; j < 16; j++) {
            int idx = tid + j * 256;
            int r = idx >> 6, d = idx & 63;
            long grow = (r0 + r) * Hc + h;
            split2(x[grow * 64 + d], &xT_hi[d * KV2 + r], &xT_lo[d * KV2 + r]);
        }
        __syncthreads();
        #pragma unroll
        for (int ks = 0; ks < 4; ks++) {
            const int k0 = ks * 16;
            unsigned ah[4], al[4];
            ah[0] = *(const unsigned*)&vpT_hi[m1 * KV2 + k0 + q2];
            ah[1] = *(const unsigned*)&vpT_hi[m2 * KV2 + k0 + q2];
            ah[2] = *(const unsigned*)&vpT_hi[m1 * KV2 + k0 + q2 + 8];
            ah[3] = *(const unsigned*)&vpT_hi[m2 * KV2 + k0 + q2 + 8];
            al[0] = *(const unsigned*)&vpT_lo[m1 * KV2 + k0 + q2];
            al[1] = *(const unsigned*)&vpT_lo[m2 * KV2 + k0 + q2];
            al[2] = *(const unsigned*)&vpT_lo[m1 * KV2 + k0 + q2 + 8];
            al[3] = *(const unsigned*)&vpT_lo[m2 * KV2 + k0 + q2 + 8];
            #pragma unroll
            for (int nt = 0; nt < 9; nt++) {
                const int n = nt * 8 + grp;
                unsigned bh0 = *(const unsigned*)&xT_hi[n * KV2 + k0 + q2];
                unsigned bh1 = *(const unsigned*)&xT_hi[n * KV2 + k0 + q2 + 8];
                unsigned bl0 = *(const unsigned*)&xT_lo[n * KV2 + k0 + q2];
                unsigned bl1 = *(const unsigned*)&xT_lo[n * KV2 + k0 + q2 + 8];
                mma_bf16(acc[nt], ah[0], ah[1], ah[2], ah[3], bh0, bh1);
                mma_bf16(acc[nt], ah[0], ah[1], ah[2], ah[3], bl0, bl1);
                mma_bf16(acc[nt], al[0], al[1], al[2], al[3], bh0, bh1);
            }
        }
        __syncthreads();
    }

    // accumulate into global v2x / v2sum
    #pragma unroll
    for (int nt = 0; nt < 8; nt++) {
        atomicAdd(&g_v2x[bh * 8192 + m1 * 64 + nt * 8 + q2],     acc[nt][0]);
        atomicAdd(&g_v2x[bh * 8192 + m1 * 64 + nt * 8 + q2 + 1], acc[nt][1]);
        atomicAdd(&g_v2x[bh * 8192 + m2 * 64 + nt * 8 + q2],     acc[nt][2]);
        atomicAdd(&g_v2x[bh * 8192 + m2 * 64 + nt * 8 + q2 + 1], acc[nt][3]);
    }
    if (q2 == 0) {
        atomicAdd(&g_v2sum[bh * 128 + m1], acc[8][0]);
        atomicAdd(&g_v2sum[bh * 128 + m2], acc[8][2]);
    }
}

// ---------------------------------------------------------------------------
// Kernel 3 (NEW, tensor cores): per (bh, 256-row chunk):
//   out1[row][d] = (v1p[row][:] . v2x[:][d]) / (v1p[row][:] . v2sum)
// GEMM M=rows(2 tiles of 128), N=72 (64 d + v2sum col + pad), K=m(128),
// bf16x3; out2 comes from column 64 of the same accumulators.
// ---------------------------------------------------------------------------
#define KO 136

__global__ void __launch_bounds__(256) k_out(const float* __restrict__ v1p,
                                             float* __restrict__ out1) {
    extern __shared__ char smraw[];
    __nv_bfloat16* A_hi = (__nv_bfloat16*)smraw;          // [128 rows][KO]
    __nv_bfloat16* A_lo = A_hi + 128 * KO;
    __nv_bfloat16* B_hi = A_lo + 128 * KO;                // [72 n][KO]
    __nv_bfloat16* B_lo = B_hi + 72 * KO;

    const int bh = blockIdx.x >> 4, ch = blockIdx.x & 15;
    const int b = bh >> 3, h = bh & 7;
    const int tid = threadIdx.x, lane = tid & 31, wid = tid >> 5;
    const int grp = lane >> 2, q2 = (lane & 3) * 2;
    const long nbase = (long)b * Nc + (long)ch * 256;

    // Load B: v2xT[d][m] from g_v2x (coalesced over d), v2sum as row 64.
    #pragma unroll
    for (int j = 0; j < 32; j++) {
        int idx = tid + j * 256;          // 0..8191
        int d = idx & 63, m = idx >> 6;
        split2(g_v2x[bh * 8192 + m * 64 + d], &B_hi[d * KO + m], &B_lo[d * KO + m]);
    }
    if (tid < 128)
        split2(g_v2sum[bh * 128 + tid], &B_hi[64 * KO + tid], &B_lo[64 * KO + tid]);
    #pragma unroll
    for (int j = 0; j < 4; j++) {
        int idx = tid + j * 256;          // 0..1023 covers 7*128=896
        if (idx < 896) {
            int n = 65 + (idx >> 7), m = idx & 127;
            B_hi[n * KO + m] = __float2bfloat16(0.0f);
            B_lo[n * KO + m] = __float2bfloat16(0.0f);
        }
    }
    __syncthreads();

    const int r1 = wid * 16 + grp, r2 = r1 + 8;  // local rows in tile

    for (int t = 0; t < 2; t++) {
        const long rbase = nbase + t * 128;
        // Load v1p tile [128 rows][128 m], split to A
        #pragma unroll
        for (int j = 0; j < 16; j++) {
            int idx4 = tid + j * 256;     // 0..4095 float4s
            int row = idx4 >> 5, c4 = idx4 & 31;
            float4 v = ((const float4*)(v1p + ((rbase + row) * Hc + h) * 128))[c4];
            float e[4] = {v.x, v.y, v.z, v.w};
            #pragma unroll
            for (int e2 = 0; e2 < 4; e2++)
                split2(e[e2], &A_hi[row * KO + c4 * 4 + e2],
                              &A_lo[row * KO + c4 * 4 + e2]);
        }
        __syncthreads();

        float acc[9][4];
        #pragma unroll
        for (int nt = 0; nt < 9; nt++)
            #pragma unroll
            for (int j = 0; j < 4; j++) acc[nt][j] = 0.f;

        #pragma unroll
        for (int ks = 0; ks < 8; ks++) {
            const int k0 = ks * 16;
            unsigned ah[4], al[4];
            ah[0] = *(const unsigned*)&A_hi[r1 * KO + k0 + q2];
            ah[1] = *(const unsigned*)&A_hi[r2 * KO + k0 + q2];
            ah[2] = *(const unsigned*)&A_hi[r1 * KO + k0 + q2 + 8];
            ah[3] = *(const unsigned*)&A_hi[r2 * KO + k0 + q2 + 8];
            al[0] = *(const unsigned*)&A_lo[r1 * KO + k0 + q2];
            al[1] = *(const unsigned*)&A_lo[r2 * KO + k0 + q2];
            al[2] = *(const unsigned*)&A_lo[r1 * KO + k0 + q2 + 8];
            al[3] = *(const unsigned*)&A_lo[r2 * KO + k0 + q2 + 8];
            #pragma unroll
            for (int nt = 0; nt < 9; nt++) {
                const int n = nt * 8 + grp;
                unsigned bh0 = *(const unsigned*)&B_hi[n * KO + k0 + q2];
                unsigned bh1 = *(const unsigned*)&B_hi[n * KO + k0 + q2 + 8];
                unsigned bl0 = *(const unsigned*)&B_lo[n * KO + k0 + q2];
                unsigned bl1 = *(const unsigned*)&B_lo[n * KO + k0 + q2 + 8];
                mma_bf16(acc[nt], ah[0], ah[1], ah[2], ah[3], bh0, bh1);
                mma_bf16(acc[nt], ah[0], ah[1], ah[2], ah[3], bl0, bl1);
                mma_bf16(acc[nt], al[0], al[1], al[2], al[3], bh0, bh1);
            }
        }

        // out2 = column 64 (held by q2==0 lanes), broadcast within quad
        float o2a = __shfl_sync(0xffffffffu, acc[8][0], lane & ~3);
        float o2b = __shfl_sync(0xffffffffu, acc[8][2], lane & ~3);
        const long grow1 = (rbase + r1) * Hc + h;
        const long grow2 = (rbase + r2) * Hc + h;
        #pragma unroll
        for (int nt = 0; nt < 8; nt++) {
            *(float2*)&out1[grow1 * 64 + nt * 8 + q2] =
                make_float2(acc[nt][0] / o2a, acc[nt][1] / o2a);
            *(float2*)&out1[grow2 * 64 + nt * 8 + q2] =
                make_float2(acc[nt][2] / o2b, acc[nt][3] / o2b);
        }
        __syncthreads();
    }
}

// ---------------------------------------------------------------------------
extern "C" void kernel_launch(void* const* d_in, const int* in_sizes, int n_in,
                              void* d_out, int out_size) {
    const float* x    = (const float*)d_in[0];
    const float* nv1  = (const float*)d_in[1];
    const float* nv2  = (const float*)d_in[2];
    const float* proj = (const float*)d_in[3];
    float* out = (float*)d_out;

    const int smem_feat = 4 * 128 * AST * 2 + 2 * 128 * 4 + 8 * 4;  // 74784 B
    const int smem_v2   = (128 * KV2 + 72 * KV2) * 2 * 2;           // 57600 B
    const int smem_out  = (128 * KO + 72 * KO) * 2 * 2;             // 108800 B
    cudaFuncSetAttribute(k_feat<true>,  cudaFuncAttributeMaxDynamicSharedMemorySize, smem_feat);
    cudaFuncSetAttribute(k_feat<false>, cudaFuncAttributeMaxDynamicSharedMemorySize, smem_feat);
    cudaFuncSetAttribute(k_v2,  cudaFuncAttributeMaxDynamicSharedMemorySize, smem_v2);
    cudaFuncSetAttribute(k_out, cudaFuncAttributeMaxDynamicSharedMemorySize, smem_out);

    k_init<<<4096, 256>>>();
    k_feat<false><<<4096, 256, smem_feat>>>(nv2, proj, nullptr);        // keys
    k_feat<true ><<<4096, 256, smem_feat>>>(nv1, proj, out + V1P_OFF);  // queries
    k_v2 <<<2048, 256, smem_v2 >>>(x, out + V2P_OFF);
    k_out<<<2048, 256, smem_out>>>(out + V1P_OFF, out);
}